// round 5
// baseline (speedup 1.0000x reference)
#include <cuda_runtime.h>
#include <cuda_bf16.h>

#define B 512
#define D 768
#define MARGIN 1.0f
#define NBLK 148

// Scratch (allocation-free rule: __device__ globals)
__device__ float g_gramp[4][B * B];  // K-split partial Gram planes, fully mirrored
__device__ float g_sqn[B];
__device__ double g_sum;
__device__ unsigned long long g_count;
__device__ unsigned int g_done;
__device__ unsigned int g_bar;       // zero at load; finisher resets each launch

union SmemU {
    struct { float As[16][68]; float Bs[16][68]; } gemm;
    struct {
        float posv[B];
        __align__(16) float negv[B + 4];
        int cnt[2];
        float ws[8];
    } trip;
};

__global__ void __launch_bounds__(256, 1)
fused_kernel(const float* __restrict__ X, const int* __restrict__ types,
             float* __restrict__ out) {
    __shared__ SmemU sm;
    int bid = blockIdx.x;
    int tid = threadIdx.x;
    int lane = tid & 31, warp = tid >> 5;

    // ======================== PHASE 1 ========================
    if (bid >= 144) {
        // ---- sq-norms + per-replay scalar reset ----
        if (bid == 147 && tid == 0) {
            g_sum = 0.0;
            g_count = 0ull;
            g_done = 0u;
        }
        int rb = (bid - 144) * 128;
        #pragma unroll
        for (int i = 0; i < 16; i++) {
            int row = rb + warp * 16 + i;
            const float4* rp = (const float4*)(X + (size_t)row * D);
            float acc = 0.f;
            #pragma unroll
            for (int q = 0; q < 6; q++) {
                float4 v = rp[lane + 32 * q];
                acc += v.x * v.x + v.y * v.y + v.z * v.z + v.w * v.w;
            }
            #pragma unroll
            for (int o = 16; o; o >>= 1) acc += __shfl_down_sync(0xffffffffu, acc, o);
            if (lane == 0) g_sqn[row] = acc;
        }
    } else {
        // ---- Gram: 64x64 triangle tiles, 4x4 micro-tile, K-split x4 ----
        int ks = bid & 3;
        int idx = bid >> 2, by = 0;
        for (;;) {
            int len = 8 - by;
            if (idx < len) break;
            idx -= len;
            by++;
        }
        int bx = by + idx;
        int rowBase = by * 64;
        int colBase = bx * 64;
        int k0 = ks * 192;

        int tx = tid & 15, ty = tid >> 4;
        int lr = tid & 63;
        int lq = tid >> 6;

        float acc[4][4];
        #pragma unroll
        for (int i = 0; i < 4; i++)
            #pragma unroll
            for (int j = 0; j < 4; j++) acc[i][j] = 0.f;

        for (int kc = 0; kc < 192; kc += 16) {
            int kk = k0 + kc + lq * 4;
            float4 av = *(const float4*)(X + (size_t)(rowBase + lr) * D + kk);
            float4 bv = *(const float4*)(X + (size_t)(colBase + lr) * D + kk);
            sm.gemm.As[lq * 4 + 0][lr] = av.x; sm.gemm.As[lq * 4 + 1][lr] = av.y;
            sm.gemm.As[lq * 4 + 2][lr] = av.z; sm.gemm.As[lq * 4 + 3][lr] = av.w;
            sm.gemm.Bs[lq * 4 + 0][lr] = bv.x; sm.gemm.Bs[lq * 4 + 1][lr] = bv.y;
            sm.gemm.Bs[lq * 4 + 2][lr] = bv.z; sm.gemm.Bs[lq * 4 + 3][lr] = bv.w;
            __syncthreads();
            #pragma unroll
            for (int k = 0; k < 16; k++) {
                float4 a4 = *(const float4*)&sm.gemm.As[k][ty * 4];
                float4 b4 = *(const float4*)&sm.gemm.Bs[k][tx * 4];
                float a[4] = {a4.x, a4.y, a4.z, a4.w};
                float b[4] = {b4.x, b4.y, b4.z, b4.w};
                #pragma unroll
                for (int i = 0; i < 4; i++)
                    #pragma unroll
                    for (int j = 0; j < 4; j++) acc[i][j] += a[i] * b[j];
            }
            __syncthreads();
        }

        float* plane = g_gramp[ks];
        #pragma unroll
        for (int i = 0; i < 4; i++) {
            int r = rowBase + ty * 4 + i;
            *(float4*)&plane[r * B + colBase + tx * 4] =
                make_float4(acc[i][0], acc[i][1], acc[i][2], acc[i][3]);
        }
        if (bx != by) {  // mirror so phase-2 reads are fully coalesced
            #pragma unroll
            for (int i = 0; i < 4; i++) {
                int r = rowBase + ty * 4 + i;
                #pragma unroll
                for (int j = 0; j < 4; j++)
                    plane[(colBase + tx * 4 + j) * B + r] = acc[i][j];
            }
        }
    }

    // ============== device-wide barrier (all 148 CTAs resident) ==============
    __threadfence();
    __syncthreads();
    if (tid == 0) {
        atomicAdd(&g_bar, 1u);
        volatile unsigned* vb = &g_bar;
        while (*vb < NBLK) { }
    }
    __syncthreads();
    __threadfence();

    // ======================== PHASE 2: triplets ========================
    double blockSum = 0.0;
    unsigned long long blockCnt = 0ull;
    unsigned lt_mask = (1u << lane) - 1u;

    for (int a = bid; a < B; a += NBLK) {
        if (tid < 2) sm.trip.cnt[tid] = 0;
        __syncthreads();

        int ta = types[a];
        float sa = g_sqn[a];
        const float* p0 = &g_gramp[0][a * B];
        const float* p1 = &g_gramp[1][a * B];
        const float* p2 = &g_gramp[2][a * B];
        const float* p3 = &g_gramp[3][a * B];

        #pragma unroll
        for (int j0 = 0; j0 < B; j0 += 256) {
            int j = j0 + tid;
            float g = p0[j] + p1[j] + p2[j] + p3[j];
            float dv = (j == a) ? 0.f
                                : sqrtf(fmaxf(sa + g_sqn[j] - 2.f * g, 0.f));
            bool isPos = (types[j] == ta);
            unsigned mp = __ballot_sync(0xffffffffu, isPos);
            int cp = __popc(mp);
            int bp = 0, bn = 0;
            if (lane == 0) {
                bp = atomicAdd(&sm.trip.cnt[0], cp);
                bn = atomicAdd(&sm.trip.cnt[1], 32 - cp);
            }
            bp = __shfl_sync(0xffffffffu, bp, 0);
            bn = __shfl_sync(0xffffffffu, bn, 0);
            if (isPos) sm.trip.posv[bp + __popc(mp & lt_mask)] = dv;
            else       sm.trip.negv[bn + __popc((~mp) & lt_mask)] = dv;
        }
        __syncthreads();

        int np = sm.trip.cnt[0], nn = sm.trip.cnt[1];
        int nn4 = (nn + 3) & ~3;
        if (tid < nn4 - nn) sm.trip.negv[nn + tid] = 1e30f;  // pad -> contributes 0
        __syncthreads();

        const float4* negv4 = (const float4*)sm.trip.negv;
        int nq = nn4 >> 2;
        float acc = 0.f;
        for (int p = warp; p < np; p += 8) {
            float dp = sm.trip.posv[p] + MARGIN;
            for (int n = lane; n < nq; n += 32) {
                float4 v = negv4[n];
                acc += fmaxf(dp - v.x, 0.f);
                acc += fmaxf(dp - v.y, 0.f);
                acc += fmaxf(dp - v.z, 0.f);
                acc += fmaxf(dp - v.w, 0.f);
            }
        }
        #pragma unroll
        for (int o = 16; o; o >>= 1) acc += __shfl_down_sync(0xffffffffu, acc, o);
        if (lane == 0) sm.trip.ws[warp] = acc;
        __syncthreads();
        if (tid == 0) {
            float s = 0.f;
            #pragma unroll
            for (int w = 0; w < 8; w++) s += sm.trip.ws[w];
            blockSum += (double)s;
            blockCnt += (unsigned long long)((long long)np * nn);
        }
        __syncthreads();
    }

    // ---- per-block accumulate, last block finalizes + resets barrier ----
    if (tid == 0) {
        atomicAdd(&g_sum, blockSum);
        atomicAdd(&g_count, blockCnt);
        __threadfence();
        unsigned d = atomicInc(&g_done, 0xffffffffu);
        if (d == NBLK - 1) {
            double S = atomicAdd(&g_sum, 0.0);
            unsigned long long C = atomicAdd(&g_count, 0ull);
            double V = (double)C;
            double b3 = 134217728.0;  // 512^3
            out[0] = (float)(((b3 - V) * (double)MARGIN + S) / V);
            __threadfence();
            g_bar = 0u;  // re-arm for the next graph replay
        }
    }
}

extern "C" void kernel_launch(void* const* d_in, const int* in_sizes, int n_in,
                              void* d_out, int out_size) {
    int ti = 0, ei = 1;
    if (in_sizes[0] == B * D) { ti = 1; ei = 0; }
    const int* types = (const int*)d_in[ti];
    const float* X = (const float*)d_in[ei];
    float* out = (float*)d_out;

    fused_kernel<<<NBLK, 256>>>(X, types, out);
}

// round 6
// speedup vs baseline: 1.3542x; 1.3542x over previous
#include <cuda_runtime.h>
#include <cuda_bf16.h>

#define B 512
#define D 768
#define MARGIN 1.0f

// Scratch (allocation-free rule: __device__ globals)
__device__ float g_gramp[4][B * B];  // K-split partial Gram planes, fully mirrored
__device__ float g_sqn[B];
__device__ double g_sum;
__device__ unsigned long long g_count;
__device__ unsigned int g_done;

// ---------------------------------------------------------------------------
// Kernel A: one wave of 148 blocks.
//   blocks 0..143  : upper-triangle Gram, 64x64 tiles, 4x4 micro-tile,
//                    K-split x4, pipelined global loads, mirrored plane stores
//   blocks 144..147: sq-norms (128 rows each) ; block 147 resets scalars
// ---------------------------------------------------------------------------
__global__ void gram_sqnorm_kernel(const float* __restrict__ X) {
    __shared__ float As[16][68];  // [k][row], padded
    __shared__ float Bs[16][68];

    int bid = blockIdx.x;
    int tid = threadIdx.x;
    int lane = tid & 31, warp = tid >> 5;

    if (bid >= 144) {
        // ---- sq-norm path + per-replay scalar reset ----
        if (bid == 147 && tid == 0) {
            g_sum = 0.0;
            g_count = 0ull;
            g_done = 0u;
        }
        int rb = (bid - 144) * 128;
        #pragma unroll
        for (int i = 0; i < 16; i++) {
            int row = rb + warp * 16 + i;
            const float4* rp = (const float4*)(X + (size_t)row * D);
            float acc = 0.f;
            #pragma unroll
            for (int q = 0; q < 6; q++) {
                float4 v = rp[lane + 32 * q];
                acc += v.x * v.x + v.y * v.y + v.z * v.z + v.w * v.w;
            }
            #pragma unroll
            for (int o = 16; o; o >>= 1) acc += __shfl_down_sync(0xffffffffu, acc, o);
            if (lane == 0) g_sqn[row] = acc;
        }
        return;
    }

    // ---- Gram path ----
    int ks = bid & 3;            // k-slice 0..3
    int idx = bid >> 2, by = 0;  // tile 0..35 -> (by, bx), bx >= by, 8x8 grid
    for (;;) {
        int len = 8 - by;
        if (idx < len) break;
        idx -= len;
        by++;
    }
    int bx = by + idx;
    int rowBase = by * 64;
    int colBase = bx * 64;

    int tx = tid & 15, ty = tid >> 4;
    int lr = tid & 63;   // row within tile for the global load
    int lq = tid >> 6;   // 0..3 -> k-quad

    const float* arow = X + (size_t)(rowBase + lr) * D + ks * 192 + lq * 4;
    const float* brow = X + (size_t)(colBase + lr) * D + ks * 192 + lq * 4;

    float acc[4][4];
    #pragma unroll
    for (int i = 0; i < 4; i++)
        #pragma unroll
        for (int j = 0; j < 4; j++) acc[i][j] = 0.f;

    // software pipeline: prefetch next K-chunk during compute
    float4 av = *(const float4*)arow;
    float4 bv = *(const float4*)brow;

    for (int kc = 0; kc < 192; kc += 16) {
        As[lq * 4 + 0][lr] = av.x; As[lq * 4 + 1][lr] = av.y;
        As[lq * 4 + 2][lr] = av.z; As[lq * 4 + 3][lr] = av.w;
        Bs[lq * 4 + 0][lr] = bv.x; Bs[lq * 4 + 1][lr] = bv.y;
        Bs[lq * 4 + 2][lr] = bv.z; Bs[lq * 4 + 3][lr] = bv.w;
        __syncthreads();
        if (kc + 16 < 192) {
            av = *(const float4*)(arow + kc + 16);
            bv = *(const float4*)(brow + kc + 16);
        }
        #pragma unroll
        for (int k = 0; k < 16; k++) {
            float4 a4 = *(const float4*)&As[k][ty * 4];
            float4 b4 = *(const float4*)&Bs[k][tx * 4];
            float a[4] = {a4.x, a4.y, a4.z, a4.w};
            float b[4] = {b4.x, b4.y, b4.z, b4.w};
            #pragma unroll
            for (int i = 0; i < 4; i++)
                #pragma unroll
                for (int j = 0; j < 4; j++) acc[i][j] += a[i] * b[j];
        }
        __syncthreads();
    }

    float* plane = g_gramp[ks];
    #pragma unroll
    for (int i = 0; i < 4; i++) {
        int r = rowBase + ty * 4 + i;
        *(float4*)&plane[r * B + colBase + tx * 4] =
            make_float4(acc[i][0], acc[i][1], acc[i][2], acc[i][3]);
    }
    if (bx != by) {
        // mirror: for fixed column c, rows rowBase+ty*4..+3 are contiguous
        #pragma unroll
        for (int j = 0; j < 4; j++) {
            int c = colBase + tx * 4 + j;
            *(float4*)&plane[c * B + rowBase + ty * 4] =
                make_float4(acc[0][j], acc[1][j], acc[2][j], acc[3][j]);
        }
    }
}

// ---------------------------------------------------------------------------
// Kernel B: one block per anchor. Coalesced 4-plane row reads; ballot
// compaction; warp-per-positive float4 hinge sum; last block finalizes.
// ---------------------------------------------------------------------------
__global__ void triplet_kernel(const int* __restrict__ types,
                               float* __restrict__ out) {
    int a = blockIdx.x;
    __shared__ float posv[B];
    __shared__ __align__(16) float negv[B + 4];
    __shared__ int cnt[2];
    __shared__ float ws[8];
    int tid = threadIdx.x;
    int lane = tid & 31, warp = tid >> 5;
    if (tid < 2) cnt[tid] = 0;
    __syncthreads();

    int ta = types[a];
    float sa = g_sqn[a];
    const float* p0 = &g_gramp[0][a * B];
    const float* p1 = &g_gramp[1][a * B];
    const float* p2 = &g_gramp[2][a * B];
    const float* p3 = &g_gramp[3][a * B];
    unsigned lt_mask = (1u << lane) - 1u;

    #pragma unroll
    for (int j0 = 0; j0 < B; j0 += 256) {
        int j = j0 + tid;
        float g = p0[j] + p1[j] + p2[j] + p3[j];
        float dv = (j == a) ? 0.f
                            : sqrtf(fmaxf(sa + g_sqn[j] - 2.f * g, 0.f));
        bool isPos = (types[j] == ta);
        unsigned mp = __ballot_sync(0xffffffffu, isPos);
        int cp = __popc(mp);
        int bp = 0, bn = 0;
        if (lane == 0) {
            bp = atomicAdd(&cnt[0], cp);
            bn = atomicAdd(&cnt[1], 32 - cp);
        }
        bp = __shfl_sync(0xffffffffu, bp, 0);
        bn = __shfl_sync(0xffffffffu, bn, 0);
        if (isPos) posv[bp + __popc(mp & lt_mask)] = dv;
        else       negv[bn + __popc((~mp) & lt_mask)] = dv;
    }
    __syncthreads();

    int np = cnt[0], nn = cnt[1];
    int nn4 = (nn + 3) & ~3;
    if (tid < nn4 - nn) negv[nn + tid] = 1e30f;  // pad -> contributes 0
    __syncthreads();

    const float4* negv4 = (const float4*)negv;
    int nq = nn4 >> 2;
    float acc = 0.f;
    for (int p = warp; p < np; p += 8) {
        float dp = posv[p] + MARGIN;
        for (int n = lane; n < nq; n += 32) {
            float4 v = negv4[n];
            acc += fmaxf(dp - v.x, 0.f);
            acc += fmaxf(dp - v.y, 0.f);
            acc += fmaxf(dp - v.z, 0.f);
            acc += fmaxf(dp - v.w, 0.f);
        }
    }

    #pragma unroll
    for (int o = 16; o; o >>= 1) acc += __shfl_down_sync(0xffffffffu, acc, o);
    if (lane == 0) ws[warp] = acc;
    __syncthreads();
    if (tid == 0) {
        float s = 0.f;
        #pragma unroll
        for (int w = 0; w < 8; w++) s += ws[w];
        atomicAdd(&g_sum, (double)s);
        atomicAdd(&g_count, (unsigned long long)((long long)np * nn));
        __threadfence();
        unsigned d = atomicInc(&g_done, 0xffffffffu);
        if (d == B - 1) {
            double S = atomicAdd(&g_sum, 0.0);
            unsigned long long C = atomicAdd(&g_count, 0ull);
            double V = (double)C;
            double b3 = 134217728.0;  // 512^3
            out[0] = (float)(((b3 - V) * (double)MARGIN + S) / V);
        }
    }
}

extern "C" void kernel_launch(void* const* d_in, const int* in_sizes, int n_in,
                              void* d_out, int out_size) {
    int ti = 0, ei = 1;
    if (in_sizes[0] == B * D) { ti = 1; ei = 0; }
    const int* types = (const int*)d_in[ti];
    const float* X = (const float*)d_in[ei];
    float* out = (float*)d_out;

    gram_sqnorm_kernel<<<148, 256>>>(X);
    triplet_kernel<<<B, 256>>>(types, out);
}